// round 12
// baseline (speedup 1.0000x reference)
#include <cuda_runtime.h>
#include <cstdint>

// ---------------- problem constants ----------------
#define Bn 16384
#define Nn 17
#define Cc 128
#define Dd 128
#define THREADS 256            // 8 warps, all GEMM (4x2 grid), all aggregate
#define MTILE 128
#define USTR 132               // U row stride: (4g+tq) distinct mod 32 -> conflict-free LDS.32

// ---------------- device scratch ----------------
__device__ float4 g_L12[Nn*Nn];      // {l1,l1,t2,t2} per (n,m)
__device__ float  g_WB[3*16*16*64];  // W as tf32 fragments, coalesced per LDG.64

// ---------------- smem: single U buffer, reused for U1 then U2 ----------------
#define SMEM_FLOATS (MTILE*USTR)     // 16896
#define SMEM_BYTES  (SMEM_FLOATS*4)  // 67584  -> 2 CTAs/SM

// ---------------- helpers ----------------
__device__ __forceinline__ uint32_t cvt_tf32(float f) {
    uint32_t u; asm("cvt.rn.tf32.f32 %0, %1;" : "=r"(u) : "f"(f)); return u;
}
__device__ __forceinline__ float tf32f(float f) { return __uint_as_float(cvt_tf32(f)); }
__device__ __forceinline__ void fma2(uint64_t& acc, uint64_t a, uint64_t b) {
    asm("fma.rn.f32x2 %0, %1, %2, %0;" : "+l"(acc) : "l"(a), "l"(b));
}
__device__ __forceinline__ void unpack2(uint64_t u, float& a, float& b) {
    asm("mov.b64 {%0, %1}, %2;" : "=f"(a), "=f"(b) : "l"(u));
}
__device__ __forceinline__ uint64_t pack2i(uint32_t a, uint32_t b) {
    uint64_t u; asm("mov.b64 %0, {%1, %2};" : "=l"(u) : "r"(a), "r"(b)); return u;
}
__device__ __forceinline__ void mma_tf32(float* d, uint32_t a0, uint32_t a1,
                                         uint32_t a2, uint32_t a3,
                                         uint32_t b0, uint32_t b1) {
    asm volatile("mma.sync.aligned.m16n8k8.row.col.f32.tf32.tf32.f32 "
        "{%0,%1,%2,%3}, {%4,%5,%6,%7}, {%8,%9}, {%0,%1,%2,%3};"
        : "+f"(d[0]), "+f"(d[1]), "+f"(d[2]), "+f"(d[3])
        : "r"(a0), "r"(a1), "r"(a2), "r"(a3), "r"(b0), "r"(b1));
}

// ---------------------------------------------------------------------------
// Merged setup: blocks 0..95 emit W fragments; block 96 computes Chebyshev basis
//   g_WB[(((k*16+s)*16)+ni)*64 + lane*2 + j]
//     = tf32( W_k[c = 8s + (lane&3) + 4j][d = (lane>>2) + 8*ni] )
// ---------------------------------------------------------------------------
__global__ void setup_kernel(const float* __restrict__ adj, const float* __restrict__ w) {
    __shared__ float dinv[Nn];
    __shared__ float Ls[Nn*Nn];
    if (blockIdx.x < 96) {
        int idx = blockIdx.x * 512 + threadIdx.x;     // < 49152
        int j  = idx & 1;
        int l  = (idx >> 1) & 31;
        int ni = (idx >> 6) & 15;
        int s  = (idx >> 10) & 15;
        int k  = idx >> 14;
        int c  = 8*s + (l & 3) + 4*j;
        int d  = (l >> 2) + 8*ni;
        g_WB[idx] = tf32f(w[k*16384 + c*128 + d]);
    } else {
        int t = threadIdx.x;
        if (t < Nn) {
            float s = 0.f;
            #pragma unroll
            for (int m = 0; m < Nn; ++m) s += adj[t*Nn + m];
            dinv[t] = rsqrtf(s);
        }
        __syncthreads();
        if (t < Nn*Nn) {
            int n = t / Nn, m = t % Nn;
            Ls[t] = (n == m ? 1.f : 0.f) - dinv[n] * adj[t] * dinv[m];
        }
        __syncthreads();
        if (t < Nn*Nn) {
            int n = t / Nn, m = t % Nn;
            float a = 0.f;
            #pragma unroll
            for (int jx = 0; jx < Nn; ++jx) a = fmaf(Ls[n*Nn + jx], Ls[jx*Nn + m], a);
            float t2 = 2.f * a - (n == m ? 1.f : 0.f);
            g_L12[t] = make_float4(Ls[t], Ls[t], t2, t2);
        }
    }
}

// ---------------------------------------------------------------------------
// GEMM chunk with A in smem (natural layout): 4x LDS.32 per mi, conflict-free.
// B frags: coalesced LDG.64 from g_WB (L1-resident after wave 1).
// ---------------------------------------------------------------------------
__device__ __forceinline__ void gemm_chunk_s(const float* Ab, const float* Bb,
                                             float acc[2][8][4]) {
    #pragma unroll 2
    for (int s = 0; s < 16; ++s) {
        const float* As = Ab + s*8;
        uint32_t A[2][4];
        #pragma unroll
        for (int mi = 0; mi < 2; ++mi) {
            const float* a = As + mi*16*USTR;
            A[mi][0] = __float_as_uint(a[0]);
            A[mi][1] = __float_as_uint(a[8*USTR]);
            A[mi][2] = __float_as_uint(a[4]);
            A[mi][3] = __float_as_uint(a[8*USTR + 4]);
        }
        uint2 B[8];
        const float* Bs = Bb + s*1024;
        #pragma unroll
        for (int ni = 0; ni < 8; ++ni) B[ni] = *(const uint2*)(Bs + ni*64);
        #pragma unroll
        for (int mi = 0; mi < 2; ++mi)
            #pragma unroll
            for (int ni = 0; ni < 8; ++ni)
                mma_tf32(acc[mi][ni], A[mi][0], A[mi][1], A[mi][2], A[mi][3],
                         B[ni].x, B[ni].y);
    }
}

// GEMM chunk 0 with A straight from gmem x (rows contiguous 512B), RN-rounded.
__device__ __forceinline__ void gemm_chunk_g(const float* Ab, const float* Bb,
                                             float acc[2][8][4]) {
    #pragma unroll 2
    for (int s = 0; s < 16; ++s) {
        const float* As = Ab + s*8;
        uint32_t A[2][4];
        #pragma unroll
        for (int mi = 0; mi < 2; ++mi) {
            const float* a = As + mi*16*128;
            A[mi][0] = cvt_tf32(a[0]);
            A[mi][1] = cvt_tf32(a[8*128]);
            A[mi][2] = cvt_tf32(a[4]);
            A[mi][3] = cvt_tf32(a[8*128 + 4]);
        }
        uint2 B[8];
        const float* Bs = Bb + s*1024;
        #pragma unroll
        for (int ni = 0; ni < 8; ++ni) B[ni] = *(const uint2*)(Bs + ni*64);
        #pragma unroll
        for (int mi = 0; mi < 2; ++mi)
            #pragma unroll
            for (int ni = 0; ni < 8; ++ni)
                mma_tf32(acc[mi][ni], A[mi][0], A[mi][1], A[mi][2], A[mi][3],
                         B[ni].x, B[ni].y);
    }
}

// ---------------------------------------------------------------------------
// Aggregation pass: U_k -> sU (natural layout), x from gmem (coalesced LDG.64)
// pass=0: U1 (L);  pass=1: U2 (T2).  All 256 threads participate.
// ---------------------------------------------------------------------------
__device__ __forceinline__ void agg_pass(float* sU, const float* __restrict__ x,
                                         int bstart, int phase, int nb,
                                         int t, int pass) {
    const ulonglong2* gL = (const ulonglong2*)g_L12;
    const int items = nb * 64;
    for (int it = t; it < items; it += THREADS) {
        const int bb = it >> 6, p = it & 63;
        const float* xb = x + (size_t)(bstart + bb) * 2176 + 2*p;
        uint64_t x2[Nn];
        #pragma unroll
        for (int m = 0; m < Nn; ++m) x2[m] = *(const uint64_t*)(xb + m*128);
        const int rb = bb*17 - phase;
        #pragma unroll 1
        for (int n = 0; n < Nn; ++n) {
            const int r = rb + n;
            if ((unsigned)r >= (unsigned)MTILE) continue;
            uint64_t a = 0ull;
            const ulonglong2* Ln = gL + n*Nn;
            #pragma unroll
            for (int m = 0; m < Nn; ++m) {
                ulonglong2 l = __ldg(Ln + m);   // {l1,l1 | t2,t2}, uniform, L1-hot
                fma2(a, x2[m], pass ? l.y : l.x);
            }
            float f0, f1;
            unpack2(a, f0, f1);
            *(uint64_t*)(sU + r*USTR + 2*p) = pack2i(cvt_tf32(f0), cvt_tf32(f1));
        }
    }
}

// ---------------------------------------------------------------------------
// Main kernel: M-tile 128, 2 CTAs/SM, phase-serial within CTA (cross-CTA overlap)
// ---------------------------------------------------------------------------
__global__ void __launch_bounds__(THREADS, 2)
graphcheb(const float* __restrict__ x, const float* __restrict__ bias,
          float* __restrict__ out) {
    extern __shared__ float sU[];

    const int t    = threadIdx.x;
    const int lane = t & 31;
    const int warp = t >> 5;
    const int g    = lane >> 2;
    const int tq   = lane & 3;

    const int rg0    = blockIdx.x * MTILE;
    const int bstart = rg0 / Nn;
    const int phase  = rg0 - bstart * Nn;
    const int nb     = (rg0 + MTILE - 1) / Nn - bstart + 1;   // <= 9

    // ---- phase 1: aggregate U1 (also warms x in L1/L2 for chunk 0) ----
    agg_pass(sU, x, bstart, phase, nb, t, 0);
    __syncthreads();

    // ---- phase 2: GEMM chunk0 (A from gmem) + chunk1 (A from sU=U1) ----
    const int mw = warp >> 1, nw = warp & 1;     // 4x2 warp grid, 32x64 tiles
    const int r0 = 32 * mw;
    const int arow = r0 + g;
    float acc[2][8][4];
    #pragma unroll
    for (int mi = 0; mi < 2; ++mi)
        #pragma unroll
        for (int ni = 0; ni < 8; ++ni)
            #pragma unroll
            for (int j = 0; j < 4; ++j) acc[mi][ni][j] = 0.f;

    gemm_chunk_g(x + (size_t)(rg0 + arow)*128 + tq,
                 g_WB + (0*256 + 8*nw)*64 + lane*2, acc);
    gemm_chunk_s(sU + arow*USTR + tq,
                 g_WB + (1*256 + 8*nw)*64 + lane*2, acc);
    __syncthreads();

    // ---- phase 3: aggregate U2 (overwrites sU) ----
    agg_pass(sU, x, bstart, phase, nb, t, 1);
    __syncthreads();

    // ---- phase 4: GEMM chunk2 + epilogue ----
    gemm_chunk_s(sU + arow*USTR + tq,
                 g_WB + (2*256 + 8*nw)*64 + lane*2, acc);

    const int d0c = 64 * nw;
    #pragma unroll
    for (int ni = 0; ni < 8; ++ni) {
        const int col = d0c + 8*ni + 2*tq;
        const float2 bv = __ldg((const float2*)(bias + col));
        #pragma unroll
        for (int mi = 0; mi < 2; ++mi) {
            const int rr = rg0 + r0 + 16*mi + g;
            float2 v0, v1;
            v0.x = fmaxf(acc[mi][ni][0] + bv.x, 0.f);
            v0.y = fmaxf(acc[mi][ni][1] + bv.y, 0.f);
            v1.x = fmaxf(acc[mi][ni][2] + bv.x, 0.f);
            v1.y = fmaxf(acc[mi][ni][3] + bv.y, 0.f);
            *(float2*)(out + (size_t)rr*Dd + col)       = v0;
            *(float2*)(out + (size_t)(rr + 8)*Dd + col) = v1;
        }
    }
}

// ---------------------------------------------------------------------------
extern "C" void kernel_launch(void* const* d_in, const int* in_sizes, int n_in,
                              void* d_out, int out_size) {
    const float* x    = (const float*)d_in[0];   // [16384,17,128]
    const float* adj  = (const float*)d_in[1];   // [17,17]
    const float* w    = (const float*)d_in[2];   // [3,1,128,128]
    const float* bias = (const float*)d_in[3];   // [1,1,128]
    float* out = (float*)d_out;                  // [16384,17,128]

    cudaFuncSetAttribute(graphcheb,
                         cudaFuncAttributeMaxDynamicSharedMemorySize, SMEM_BYTES);

    setup_kernel<<<97, 512>>>(adj, w);
    graphcheb<<<(Bn*Nn)/MTILE, THREADS, SMEM_BYTES>>>(x, bias, out);
}

// round 13
// speedup vs baseline: 1.0259x; 1.0259x over previous
#include <cuda_runtime.h>
#include <cstdint>

// ---------------- problem constants ----------------
#define Bn 16384
#define Nn 17
#define Cc 128
#define Dd 128
#define THREADS 256            // 8 warps (4x2 GEMM grid), serial phases, 2 CTAs/SM
#define MTILE 128
#define USTR 132               // (4g+tq) distinct mod 32 -> conflict-free LDS.32 frags

// ---------------- device scratch ----------------
__device__ float4 g_L12[Nn*Nn];      // {l1,l1,t2,t2} per (n,m)
__device__ float  g_WB[3*16*16*64];  // W tf32 fragments; per (k,s,nw): 16 contiguous floats/lane

// ---------------- smem: one U/X buffer + L table ----------------
#define SF_U 0                       // 128*132 = 16896 floats
#define SF_L 16896                   // 289 float4 = 1156 floats
#define SMEM_FLOATS (16896 + 1156)
#define SMEM_BYTES  (SMEM_FLOATS*4)  // 72208 -> 2 CTAs/SM

// ---------------- helpers ----------------
__device__ __forceinline__ uint32_t cvt_tf32(float f) {
    uint32_t u; asm("cvt.rn.tf32.f32 %0, %1;" : "=r"(u) : "f"(f)); return u;
}
__device__ __forceinline__ float tf32f(float f) { return __uint_as_float(cvt_tf32(f)); }
__device__ __forceinline__ void fma2(uint64_t& acc, uint64_t a, uint64_t b) {
    asm("fma.rn.f32x2 %0, %1, %2, %0;" : "+l"(acc) : "l"(a), "l"(b));
}
__device__ __forceinline__ void unpack2(uint64_t u, float& a, float& b) {
    asm("mov.b64 {%0, %1}, %2;" : "=f"(a), "=f"(b) : "l"(u));
}
__device__ __forceinline__ uint64_t pack2i(uint32_t a, uint32_t b) {
    uint64_t u; asm("mov.b64 %0, {%1, %2};" : "=l"(u) : "r"(a), "r"(b)); return u;
}
__device__ __forceinline__ void mma_tf32(float* d, uint32_t a0, uint32_t a1,
                                         uint32_t a2, uint32_t a3,
                                         uint32_t b0, uint32_t b1) {
    asm volatile("mma.sync.aligned.m16n8k8.row.col.f32.tf32.tf32.f32 "
        "{%0,%1,%2,%3}, {%4,%5,%6,%7}, {%8,%9}, {%0,%1,%2,%3};"
        : "+f"(d[0]), "+f"(d[1]), "+f"(d[2]), "+f"(d[3])
        : "r"(a0), "r"(a1), "r"(a2), "r"(a3), "r"(b0), "r"(b1));
}

// ---------------------------------------------------------------------------
// Merged setup. W fragment layout (new, LDG.128-friendly):
//   g_WB[((k*16+s)*2+nw)*512 + lane*16 + ni*2 + j]
//     = tf32( W_k[c = 8s + (lane&3) + 4j][d = (lane>>2) + 8*ni + 64*nw] )
// so each lane's 8 B-frags per k-step are 16 contiguous floats (4x LDG.128).
// ---------------------------------------------------------------------------
__global__ void setup_kernel(const float* __restrict__ adj, const float* __restrict__ w) {
    __shared__ float dinv[Nn];
    __shared__ float Ls[Nn*Nn];
    if (blockIdx.x < 96) {
        int idx = blockIdx.x * 512 + threadIdx.x;     // < 49152
        int j    = idx & 1;
        int ni   = (idx >> 1) & 7;
        int lane = (idx >> 4) & 31;
        int nw   = (idx >> 9) & 1;
        int s    = (idx >> 10) & 15;
        int k    = idx >> 14;
        int c = 8*s + (lane & 3) + 4*j;
        int d = (lane >> 2) + 8*ni + 64*nw;
        g_WB[idx] = tf32f(w[k*16384 + c*128 + d]);
    } else {
        int t = threadIdx.x;
        if (t < Nn) {
            float s = 0.f;
            #pragma unroll
            for (int m = 0; m < Nn; ++m) s += adj[t*Nn + m];
            dinv[t] = rsqrtf(s);
        }
        __syncthreads();
        if (t < Nn*Nn) {
            int n = t / Nn, m = t % Nn;
            Ls[t] = (n == m ? 1.f : 0.f) - dinv[n] * adj[t] * dinv[m];
        }
        __syncthreads();
        if (t < Nn*Nn) {
            int n = t / Nn, m = t % Nn;
            float a = 0.f;
            #pragma unroll
            for (int jx = 0; jx < Nn; ++jx) a = fmaf(Ls[n*Nn + jx], Ls[jx*Nn + m], a);
            float t2 = 2.f * a - (n == m ? 1.f : 0.f);
            g_L12[t] = make_float4(Ls[t], Ls[t], t2, t2);
        }
    }
}

// ---------------------------------------------------------------------------
// GEMM chunk: A frags 8x LDS.32 (conflict-free), B frags 4x LDG.128 (L1-hot)
// ---------------------------------------------------------------------------
__device__ __forceinline__ void gemm_chunk(const float* Ab, const float* Bb,
                                           float acc[2][8][4]) {
    #pragma unroll 2
    for (int s = 0; s < 16; ++s) {
        const float* As = Ab + s*8;
        uint32_t A[2][4];
        #pragma unroll
        for (int mi = 0; mi < 2; ++mi) {
            const float* a = As + mi*16*USTR;
            A[mi][0] = __float_as_uint(a[0]);
            A[mi][1] = __float_as_uint(a[8*USTR]);
            A[mi][2] = __float_as_uint(a[4]);
            A[mi][3] = __float_as_uint(a[8*USTR + 4]);
        }
        uint4 B4[4];
        const float* Bs = Bb + s*1024;
        #pragma unroll
        for (int q = 0; q < 4; ++q) B4[q] = *(const uint4*)(Bs + q*4);
        #pragma unroll
        for (int mi = 0; mi < 2; ++mi)
            #pragma unroll
            for (int q = 0; q < 4; ++q) {
                mma_tf32(acc[mi][2*q],   A[mi][0], A[mi][1], A[mi][2], A[mi][3],
                         B4[q].x, B4[q].y);
                mma_tf32(acc[mi][2*q+1], A[mi][0], A[mi][1], A[mi][2], A[mi][3],
                         B4[q].z, B4[q].w);
            }
    }
}

// ---------------------------------------------------------------------------
// Main kernel: serial phases, 2 CTAs/SM for cross-CTA overlap.
//   agg(U1->smem, U2->out stash) ; chunk1 ; x->smem ; chunk0 ;
//   U2 reload ; chunk2 ; epilogue (overwrites out)
// ---------------------------------------------------------------------------
__global__ void __launch_bounds__(THREADS, 2)
graphcheb(const float* __restrict__ x, const float* __restrict__ bias,
          float* __restrict__ out) {
    extern __shared__ float sm[];
    float* sU = sm + SF_U;
    float* sL = sm + SF_L;

    const int t    = threadIdx.x;
    const int lane = t & 31;
    const int warp = t >> 5;
    const int g    = lane >> 2;
    const int tq   = lane & 3;

    const int rg0    = blockIdx.x * MTILE;
    const int bstart = rg0 / Nn;
    const int phase  = rg0 - bstart * Nn;
    const int nb     = (rg0 + MTILE - 1) / Nn - bstart + 1;   // 8 or 9

    // ---- L table -> smem ----
    for (int i = t; i < Nn*Nn*4; i += THREADS) sL[i] = ((const float*)g_L12)[i];
    __syncthreads();

    // ---- phase A: fused aggregation (acc dead). U1 -> sU, U2 -> out stash ----
    {
        const int items = nb * 64;
        for (int it = t; it < items; it += THREADS) {
            const int bb = it >> 6, p = it & 63;
            const uint64_t* xb = (const uint64_t*)(x + (size_t)(bstart + bb)*2176 + 2*p);
            uint64_t x2[Nn];
            #pragma unroll
            for (int m = 0; m < Nn; ++m) x2[m] = xb[m*64];   // coalesced LDG.64
            const int rb = bb*17 - phase;
            #pragma unroll 1
            for (int n = 0; n < Nn; ++n) {
                const int r = rb + n;
                if ((unsigned)r >= (unsigned)MTILE) continue;
                uint64_t a1 = 0ull, a2 = 0ull;
                const ulonglong2* Ln = (const ulonglong2*)sL + n*Nn;
                #pragma unroll
                for (int m = 0; m < Nn; ++m) {
                    ulonglong2 l = Ln[m];          // LDS.128 broadcast {l1,l1 | t2,t2}
                    fma2(a1, x2[m], l.x);
                    fma2(a2, x2[m], l.y);
                }
                float f0, f1;
                unpack2(a1, f0, f1);
                *(uint64_t*)(sU + r*USTR + 2*p) = pack2i(cvt_tf32(f0), cvt_tf32(f1));
                unpack2(a2, f0, f1);
                *(uint64_t*)(out + (size_t)(rg0 + r)*128 + 2*p) =
                    pack2i(cvt_tf32(f0), cvt_tf32(f1));      // stash U2 (tf32 bits)
            }
        }
    }
    __syncthreads();

    // ---- GEMM state: 4x2 warp grid, 32x64 tiles ----
    const int mw = warp >> 1, nw = warp & 1;
    const int r0 = 32 * mw;
    const int arow = r0 + g;
    float acc[2][8][4];
    #pragma unroll
    for (int mi = 0; mi < 2; ++mi)
        #pragma unroll
        for (int ni = 0; ni < 8; ++ni)
            #pragma unroll
            for (int j = 0; j < 4; ++j) acc[mi][ni][j] = 0.f;

    // ---- chunk 1: A = U1 ----
    gemm_chunk(sU + arow*USTR + tq, g_WB + (1*32 + nw)*512 + lane*16, acc);
    __syncthreads();

    // ---- stage x rows rg0..+127 (tf32) into sU ----
    for (int i = t; i < MTILE*64; i += THREADS) {
        const int row = i >> 6, p = i & 63;
        const float2 v = *(const float2*)(x + (size_t)(rg0 + row)*128 + 2*p);
        *(uint64_t*)(sU + row*USTR + 2*p) = pack2i(cvt_tf32(v.x), cvt_tf32(v.y));
    }
    __syncthreads();

    // ---- chunk 0: A = x ----
    gemm_chunk(sU + arow*USTR + tq, g_WB + (0*32 + nw)*512 + lane*16, acc);
    __syncthreads();

    // ---- reload U2 stash from out into sU (raw tf32 bits) ----
    for (int i = t; i < MTILE*64; i += THREADS) {
        const int row = i >> 6, p = i & 63;
        uint64_t v = *(const uint64_t*)(out + (size_t)(rg0 + row)*128 + 2*p);
        *(uint64_t*)(sU + row*USTR + 2*p) = v;
    }
    __syncthreads();

    // ---- chunk 2: A = U2 ----
    gemm_chunk(sU + arow*USTR + tq, g_WB + (2*32 + nw)*512 + lane*16, acc);

    // ---- epilogue: bias + relu (overwrites stash rows completely) ----
    const int d0c = 64 * nw;
    #pragma unroll
    for (int ni = 0; ni < 8; ++ni) {
        const int col = d0c + 8*ni + 2*tq;
        const float2 bv = __ldg((const float2*)(bias + col));
        #pragma unroll
        for (int mi = 0; mi < 2; ++mi) {
            const int rr = rg0 + r0 + 16*mi + g;
            float2 v0, v1;
            v0.x = fmaxf(acc[mi][ni][0] + bv.x, 0.f);
            v0.y = fmaxf(acc[mi][ni][1] + bv.y, 0.f);
            v1.x = fmaxf(acc[mi][ni][2] + bv.x, 0.f);
            v1.y = fmaxf(acc[mi][ni][3] + bv.y, 0.f);
            *(float2*)(out + (size_t)rr*Dd + col)       = v0;
            *(float2*)(out + (size_t)(rr + 8)*Dd + col) = v1;
        }
    }
}

// ---------------------------------------------------------------------------
extern "C" void kernel_launch(void* const* d_in, const int* in_sizes, int n_in,
                              void* d_out, int out_size) {
    const float* x    = (const float*)d_in[0];   // [16384,17,128]
    const float* adj  = (const float*)d_in[1];   // [17,17]
    const float* w    = (const float*)d_in[2];   // [3,1,128,128]
    const float* bias = (const float*)d_in[3];   // [1,1,128]
    float* out = (float*)d_out;                  // [16384,17,128]

    cudaFuncSetAttribute(graphcheb,
                         cudaFuncAttributeMaxDynamicSharedMemorySize, SMEM_BYTES);

    setup_kernel<<<97, 512>>>(adj, w);
    graphcheb<<<(Bn*Nn)/MTILE, THREADS, SMEM_BYTES>>>(x, bias, out);
}

// round 14
// speedup vs baseline: 1.0880x; 1.0606x over previous
#include <cuda_runtime.h>
#include <cstdint>

// ---------------- problem constants ----------------
#define Bn 16384
#define Nn 17
#define Cc 128
#define Dd 128
#define THREADS 256            // 8 warps (4x2 GEMM grid), serial phases, 2 CTAs/SM
#define MTILE 128
#define USTR 136               // pair-permuted row stride (mod 32 == 8, R8-proven)

// ---------------- device / constant scratch ----------------
__device__ float4     g_L12[Nn*Nn];     // {l1,l1,t2,t2} per (n,m), staged to cL
__constant__ ulonglong2 cL[Nn*Nn];      // same data, constant bank (off-LSU reads)
__device__ float      g_WB[3*16*16*64]; // W tf32 frags; 16 contiguous floats/lane/k-step

// ---------------- smem: one pair-permuted U/X buffer ----------------
#define SMEM_FLOATS (MTILE*USTR)        // 17408
#define SMEM_BYTES  (SMEM_FLOATS*4)     // 69632 -> 2 CTAs/SM

// ---------------- helpers ----------------
__device__ __forceinline__ uint32_t cvt_tf32(float f) {
    uint32_t u; asm("cvt.rn.tf32.f32 %0, %1;" : "=r"(u) : "f"(f)); return u;
}
__device__ __forceinline__ float tf32f(float f) { return __uint_as_float(cvt_tf32(f)); }
__device__ __forceinline__ void fma2(uint64_t& acc, uint64_t a, uint64_t b) {
    asm("fma.rn.f32x2 %0, %1, %2, %0;" : "+l"(acc) : "l"(a), "l"(b));
}
__device__ __forceinline__ void unpack2(uint64_t u, float& a, float& b) {
    asm("mov.b64 {%0, %1}, %2;" : "=f"(a), "=f"(b) : "l"(u));
}
__device__ __forceinline__ uint64_t pack2i(uint32_t a, uint32_t b) {
    uint64_t u; asm("mov.b64 %0, {%1, %2};" : "=l"(u) : "r"(a), "r"(b)); return u;
}
__device__ __forceinline__ void mma_tf32(float* d, uint32_t a0, uint32_t a1,
                                         uint32_t a2, uint32_t a3,
                                         uint32_t b0, uint32_t b1) {
    asm volatile("mma.sync.aligned.m16n8k8.row.col.f32.tf32.tf32.f32 "
        "{%0,%1,%2,%3}, {%4,%5,%6,%7}, {%8,%9}, {%0,%1,%2,%3};"
        : "+f"(d[0]), "+f"(d[1]), "+f"(d[2]), "+f"(d[3])
        : "r"(a0), "r"(a1), "r"(a2), "r"(a3), "r"(b0), "r"(b1));
}

// ---------------------------------------------------------------------------
// Merged setup. W fragment layout (LDG.128-friendly, as R13):
//   g_WB[((k*16+s)*2+nw)*512 + lane*16 + ni*2 + j]
//     = tf32( W_k[c = 8s + (lane&3) + 4j][d = (lane>>2) + 8*ni + 64*nw] )
// Block 96 computes the Chebyshev basis into g_L12.
// ---------------------------------------------------------------------------
__global__ void setup_kernel(const float* __restrict__ adj, const float* __restrict__ w) {
    __shared__ float dinv[Nn];
    __shared__ float Ls[Nn*Nn];
    if (blockIdx.x < 96) {
        int idx = blockIdx.x * 512 + threadIdx.x;     // < 49152
        int j    = idx & 1;
        int ni   = (idx >> 1) & 7;
        int lane = (idx >> 4) & 31;
        int nw   = (idx >> 9) & 1;
        int s    = (idx >> 10) & 15;
        int k    = idx >> 14;
        int c = 8*s + (lane & 3) + 4*j;
        int d = (lane >> 2) + 8*ni + 64*nw;
        g_WB[idx] = tf32f(w[k*16384 + c*128 + d]);
    } else {
        int t = threadIdx.x;
        if (t < Nn) {
            float s = 0.f;
            #pragma unroll
            for (int m = 0; m < Nn; ++m) s += adj[t*Nn + m];
            dinv[t] = rsqrtf(s);
        }
        __syncthreads();
        if (t < Nn*Nn) {
            int n = t / Nn, m = t % Nn;
            Ls[t] = (n == m ? 1.f : 0.f) - dinv[n] * adj[t] * dinv[m];
        }
        __syncthreads();
        if (t < Nn*Nn) {
            int n = t / Nn, m = t % Nn;
            float a = 0.f;
            #pragma unroll
            for (int jx = 0; jx < Nn; ++jx) a = fmaf(Ls[n*Nn + jx], Ls[jx*Nn + m], a);
            float t2 = 2.f * a - (n == m ? 1.f : 0.f);
            g_L12[t] = make_float4(Ls[t], Ls[t], t2, t2);
        }
    }
}

// ---------------------------------------------------------------------------
// GEMM chunk: A frags 2x LDS.64 (pair-permuted, conflict-free),
//             B frags 4x LDG.128 (L1-hot after wave 1)
// ---------------------------------------------------------------------------
__device__ __forceinline__ void gemm_chunk(const float* Ab, const float* Bb,
                                           float acc[2][8][4]) {
    #pragma unroll 2
    for (int s = 0; s < 16; ++s) {
        const float* As = Ab + s*8;
        uint2 A[2][2];
        #pragma unroll
        for (int mi = 0; mi < 2; ++mi) {
            A[mi][0] = *(const uint2*)(As + mi*16*USTR);           // {a0,a2} row g
            A[mi][1] = *(const uint2*)(As + mi*16*USTR + 8*USTR);  // {a1,a3} row g+8
        }
        uint4 B4[4];
        const float* Bs = Bb + s*1024;
        #pragma unroll
        for (int q = 0; q < 4; ++q) B4[q] = *(const uint4*)(Bs + q*4);
        #pragma unroll
        for (int mi = 0; mi < 2; ++mi)
            #pragma unroll
            for (int q = 0; q < 4; ++q) {
                mma_tf32(acc[mi][2*q],   A[mi][0].x, A[mi][1].x,
                         A[mi][0].y, A[mi][1].y, B4[q].x, B4[q].y);
                mma_tf32(acc[mi][2*q+1], A[mi][0].x, A[mi][1].x,
                         A[mi][0].y, A[mi][1].y, B4[q].z, B4[q].w);
            }
    }
}

// ---------------------------------------------------------------------------
// Main kernel: serial phases, 2 CTAs/SM (cross-CTA overlap).
//   agg (L from constant bank; U1->sU, U2->out stash) ; chunk1 ;
//   x->sU ; chunk0 ; U2 reload ; chunk2 ; epilogue
// ---------------------------------------------------------------------------
__global__ void __launch_bounds__(THREADS, 2)
graphcheb(const float* __restrict__ x, const float* __restrict__ bias,
          float* __restrict__ out) {
    extern __shared__ float sU[];

    const int t    = threadIdx.x;
    const int lane = t & 31;
    const int warp = t >> 5;
    const int g    = lane >> 2;
    const int tq   = lane & 3;

    const int rg0    = blockIdx.x * MTILE;
    const int bstart = rg0 / Nn;
    const int phase  = rg0 - bstart * Nn;
    const int nb     = (rg0 + MTILE - 1) / Nn - bstart + 1;   // 8 or 9

    // ---- phase A: fused aggregation. item = (batch, quad of 4 cols) ----
    // U1 -> sU (pair-permuted tf32), U2 -> out stash (tf32 bits)
    {
        const int items = nb * 32;
        for (int it = t; it < items; it += THREADS) {
            const int bb = it >> 5, q = it & 31;
            const int cp0 = (q >> 1) * 8 + ((2*q) & 3);      // cols cp0,cp0+1,cp0+4,cp0+5
            const float* xb = x + (size_t)(bstart + bb)*2176 + cp0;
            uint64_t xp0[Nn], xp1[Nn];                        // pair-major x
            #pragma unroll
            for (int m = 0; m < Nn; ++m) {
                uint2 a = *(const uint2*)(xb + m*128);        // {c, c+1}
                uint2 b = *(const uint2*)(xb + m*128 + 4);    // {c+4, c+5}
                xp0[m] = pack2i(a.x, b.x);                    // {c,   c+4}
                xp1[m] = pack2i(a.y, b.y);                    // {c+1, c+5}
            }
            const int rb = bb*17 - phase;
            #pragma unroll 1
            for (int n = 0; n < Nn; ++n) {
                const int r = rb + n;
                if ((unsigned)r >= (unsigned)MTILE) continue;
                uint64_t a1p0 = 0ull, a1p1 = 0ull, a2p0 = 0ull, a2p1 = 0ull;
                #pragma unroll
                for (int m = 0; m < Nn; ++m) {
                    ulonglong2 l = cL[n*Nn + m];   // constant port: {l1,l1 | t2,t2}
                    fma2(a1p0, xp0[m], l.x);
                    fma2(a1p1, xp1[m], l.x);
                    fma2(a2p0, xp0[m], l.y);
                    fma2(a2p1, xp1[m], l.y);
                }
                float f0, f1, f2, f3;
                uint4 o;
                unpack2(a1p0, f0, f1); unpack2(a1p1, f2, f3);
                o.x = cvt_tf32(f0); o.y = cvt_tf32(f1);
                o.z = cvt_tf32(f2); o.w = cvt_tf32(f3);
                *(uint4*)(sU + r*USTR + 4*q) = o;                         // U1
                unpack2(a2p0, f0, f1); unpack2(a2p1, f2, f3);
                o.x = cvt_tf32(f0); o.y = cvt_tf32(f1);
                o.z = cvt_tf32(f2); o.w = cvt_tf32(f3);
                *(uint4*)(out + (size_t)(rg0 + r)*128 + 4*q) = o;         // U2 stash
            }
        }
    }
    __syncthreads();

    // ---- GEMM state: 4x2 warp grid, 32x64 tiles ----
    const int mw = warp >> 1, nw = warp & 1;
    const int r0 = 32 * mw;
    const int arow = r0 + g;
    float acc[2][8][4];
    #pragma unroll
    for (int mi = 0; mi < 2; ++mi)
        #pragma unroll
        for (int ni = 0; ni < 8; ++ni)
            #pragma unroll
            for (int j = 0; j < 4; ++j) acc[mi][ni][j] = 0.f;

    // ---- chunk 1: A = U1 ----
    gemm_chunk(sU + arow*USTR + 2*tq, g_WB + (1*32 + nw)*512 + lane*16, acc);
    __syncthreads();

    // ---- stage x rows (tf32, pair-permuted) into sU ----
    for (int i = t; i < MTILE*16; i += THREADS) {
        const int row = i >> 4, o = i & 15;                  // 8 cols per item
        const float* p = x + (size_t)(rg0 + row)*128 + o*8;
        float4 v0 = *(const float4*)p;
        float4 v1 = *(const float4*)(p + 4);
        uint4 w0, w1;
        w0.x = cvt_tf32(v0.x); w0.y = cvt_tf32(v1.x);        // pair {c,  c+4}
        w0.z = cvt_tf32(v0.y); w0.w = cvt_tf32(v1.y);        // pair {c+1,c+5}
        w1.x = cvt_tf32(v0.z); w1.y = cvt_tf32(v1.z);
        w1.z = cvt_tf32(v0.w); w1.w = cvt_tf32(v1.w);
        *(uint4*)(sU + row*USTR + o*8)     = w0;
        *(uint4*)(sU + row*USTR + o*8 + 4) = w1;
    }
    __syncthreads();

    // ---- chunk 0: A = x ----
    gemm_chunk(sU + arow*USTR + 2*tq, g_WB + (0*32 + nw)*512 + lane*16, acc);
    __syncthreads();

    // ---- reload U2 stash into sU (raw tf32 bits, already pair-permuted) ----
    for (int i = t; i < MTILE*32; i += THREADS) {
        const int row = i >> 5, q = i & 31;
        uint4 v = *(const uint4*)(out + (size_t)(rg0 + row)*128 + 4*q);
        *(uint4*)(sU + row*USTR + 4*q) = v;
    }
    __syncthreads();

    // ---- chunk 2: A = U2 ----
    gemm_chunk(sU + arow*USTR + 2*tq, g_WB + (2*32 + nw)*512 + lane*16, acc);

    // ---- epilogue: bias + relu (fully overwrites the stash rows) ----
    const int d0c = 64 * nw;
    #pragma unroll
    for (int ni = 0; ni < 8; ++ni) {
        const int col = d0c + 8*ni + 2*tq;
        const float2 bv = __ldg((const float2*)(bias + col));
        #pragma unroll
        for (int mi = 0; mi < 2; ++mi) {
            const int rr = rg0 + r0 + 16*mi + g;
            float2 v0, v1;
            v0.x = fmaxf(acc[mi][ni][0] + bv.x, 0.f);
            v0.y = fmaxf(acc[mi][ni][1] + bv.y, 0.f);
            v1.x = fmaxf(acc[mi][ni][2] + bv.x, 0.f);
            v1.y = fmaxf(acc[mi][ni][3] + bv.y, 0.f);
            *(float2*)(out + (size_t)rr*Dd + col)       = v0;
            *(float2*)(out + (size_t)(rr + 8)*Dd + col) = v1;
        }
    }
}

// ---------------------------------------------------------------------------
extern "C" void kernel_launch(void* const* d_in, const int* in_sizes, int n_in,
                              void* d_out, int out_size) {
    const float* x    = (const float*)d_in[0];   // [16384,17,128]
    const float* adj  = (const float*)d_in[1];   // [17,17]
    const float* w    = (const float*)d_in[2];   // [3,1,128,128]
    const float* bias = (const float*)d_in[3];   // [1,1,128]
    float* out = (float*)d_out;                  // [16384,17,128]

    cudaFuncSetAttribute(graphcheb,
                         cudaFuncAttributeMaxDynamicSharedMemorySize, SMEM_BYTES);

    setup_kernel<<<97, 512>>>(adj, w);

    // stage L into the constant bank (graph-legal D2D memcpy node)
    void* lsrc = nullptr;
    cudaGetSymbolAddress(&lsrc, g_L12);
    cudaMemcpyToSymbolAsync(cL, lsrc, sizeof(float4)*Nn*Nn, 0,
                            cudaMemcpyDeviceToDevice, 0);

    graphcheb<<<(Bn*Nn)/MTILE, THREADS, SMEM_BYTES>>>(x, bias, out);
}